// round 8
// baseline (speedup 1.0000x reference)
#include <cuda_runtime.h>
#include <cstdint>

// LSTM B=4096 T=256 I=8 H=32 O=1.
// NB=8: warp = 8 batches; lane j = hidden unit j. f32x2 lanes are GATE pairs
// {z_i,z_f},{z_g,z_o}; 16 independent fma2 accumulator chains per warp give a
// single warp enough ILP to self-saturate the fma pipe (1 warp/SMSP).
// W_hh in 128 regs as gate pairs; W_ih in smem. h and x pre-duplicated
// ({v,v} u64) in shared -> broadcast LDS.128, zero packs in hot loop.
// Sigmoid 0.5 folded into weights/biases (i,f,o).
// CTA = 128 thr (4 warps, 32 batches), grid = 128 -> exactly 1 CTA per SM.

#define B_TOT 4096
#define T_TOT 256
#define I_SZ 8
#define CHUNK 8

// shared strides (in u64 units)
#define HK_STRIDE 10            // 8 batch-dups + 2 pad; 80B, 16B-aligned
#define XI_STRIDE 10
#define XT_STRIDE 82            // 8*10 + 2 pad; 656B, 16B-aligned

typedef unsigned long long u64;

__device__ __forceinline__ u64 pack2(float a, float b) {
    u64 r; asm("mov.b64 %0,{%1,%2};" : "=l"(r) : "f"(a), "f"(b)); return r;
}
__device__ __forceinline__ void unpack2(u64 v, float& a, float& b) {
    asm("mov.b64 {%0,%1},%2;" : "=f"(a), "=f"(b) : "l"(v));
}
__device__ __forceinline__ u64 fma2(u64 a, u64 b, u64 c) {
    u64 d; asm("fma.rn.f32x2 %0,%1,%2,%3;" : "=l"(d) : "l"(a), "l"(b), "l"(c)); return d;
}
__device__ __forceinline__ float tanhap(float x) {
    float y; asm("tanh.approx.f32 %0,%1;" : "=f"(y) : "f"(x)); return y;
}
// i,f,o accumulators pre-scaled by 0.5: sigmoid(z)=0.5*tanh(z/2)+0.5
__device__ __forceinline__ float sig_h(float zhalf) {
    return fmaf(0.5f, tanhap(zhalf), 0.5f);
}

__global__ void __launch_bounds__(128)
lstm_kernel(const float* __restrict__ x,
            const float* __restrict__ W_ih,
            const float* __restrict__ W_hh,
            const float* __restrict__ b_ih,
            const float* __restrict__ b_hh,
            const float* __restrict__ W_out,
            const float* __restrict__ b_out,
            float* __restrict__ out)
{
    __shared__ __align__(16) ulonglong2 wi_sm[I_SZ * 32];        // [i][j] {wif},{wgo}
    __shared__ __align__(16) u64 xbuf[4][CHUNK * XT_STRIDE];     // per-warp x dup
    __shared__ __align__(16) u64 hbuf[4][2 * 32 * HK_STRIDE];    // per-warp h dup, dbl-buf

    const int tid  = threadIdx.x;
    const int lane = tid & 31;
    const int warp = tid >> 5;

    // ---- W_hh rows -> registers as gate pairs (i,f,o pre-scaled by 0.5) ----
    u64 wif[32], wgo[32];
    {
        const float* ri = W_hh + (0 * 32 + lane) * 32;
        const float* rf = W_hh + (1 * 32 + lane) * 32;
        const float* rg = W_hh + (2 * 32 + lane) * 32;
        const float* ro = W_hh + (3 * 32 + lane) * 32;
#pragma unroll
        for (int kk = 0; kk < 8; ++kk) {
            const float4 ai = *(const float4*)(ri + kk * 4);
            const float4 af = *(const float4*)(rf + kk * 4);
            const float4 ag = *(const float4*)(rg + kk * 4);
            const float4 ao = *(const float4*)(ro + kk * 4);
            wif[kk * 4 + 0] = pack2(0.5f * ai.x, 0.5f * af.x);
            wif[kk * 4 + 1] = pack2(0.5f * ai.y, 0.5f * af.y);
            wif[kk * 4 + 2] = pack2(0.5f * ai.z, 0.5f * af.z);
            wif[kk * 4 + 3] = pack2(0.5f * ai.w, 0.5f * af.w);
            wgo[kk * 4 + 0] = pack2(ag.x, 0.5f * ao.x);
            wgo[kk * 4 + 1] = pack2(ag.y, 0.5f * ao.y);
            wgo[kk * 4 + 2] = pack2(ag.z, 0.5f * ao.z);
            wgo[kk * 4 + 3] = pack2(ag.w, 0.5f * ao.w);
        }
    }

    // ---- W_ih gate pairs into smem ----
    for (int idx = tid; idx < I_SZ * 32; idx += 128) {
        int i = idx >> 5, j = idx & 31;
        float a = 0.5f * W_ih[(0 * 32 + j) * I_SZ + i];
        float b = 0.5f * W_ih[(1 * 32 + j) * I_SZ + i];
        float c =        W_ih[(2 * 32 + j) * I_SZ + i];
        float d = 0.5f * W_ih[(3 * 32 + j) * I_SZ + i];
        wi_sm[idx] = make_ulonglong2(pack2(a, b), pack2(c, d));
    }
    // ---- zero h buffers ----
    for (int idx = tid; idx < 4 * 2 * 32 * HK_STRIDE; idx += 128)
        ((u64*)hbuf)[idx] = 0ull;
    __syncthreads();

    // ---- biases (gate pairs, i/f/o pre-scaled) ----
    const float bi_ = 0.5f * (b_ih[0 * 32 + lane] + b_hh[0 * 32 + lane]);
    const float bf_ = 0.5f * (b_ih[1 * 32 + lane] + b_hh[1 * 32 + lane]);
    const float bg_ =         b_ih[2 * 32 + lane] + b_hh[2 * 32 + lane];
    const float bo_ = 0.5f * (b_ih[3 * 32 + lane] + b_hh[3 * 32 + lane]);
    const u64 bif = pack2(bi_, bf_);
    const u64 bgo = pack2(bg_, bo_);

    float cs[8], hs[8];
#pragma unroll
    for (int b = 0; b < 8; ++b) { cs[b] = 0.f; hs[b] = 0.f; }

    u64* const xW = xbuf[warp];
    u64* const hW = hbuf[warp];
    int cur = 0;

    // this warp's 8 batches
    const float* xw = x + (size_t)(blockIdx.x * 32 + warp * 8) * T_TOT * I_SZ;
    const int t_ = lane >> 2;           // 0..7
    const int i0 = (lane & 3) * 2;      // 0,2,4,6

#pragma unroll 1
    for (int tc = 0; tc < T_TOT / CHUNK; ++tc) {
        __syncwarp();
        // ---- stage x chunk, pre-duplicated {x,x}; lane covers (t_, i0..i0+1) ----
#pragma unroll
        for (int b = 0; b < 8; ++b) {
            const float2 v = *(const float2*)(xw
                + ((size_t)b * T_TOT + tc * CHUNK + t_) * I_SZ + i0);
            xW[t_ * XT_STRIDE + (i0 + 0) * XI_STRIDE + b] = pack2(v.x, v.x);
            xW[t_ * XT_STRIDE + (i0 + 1) * XI_STRIDE + b] = pack2(v.y, v.y);
        }
        __syncwarp();

#pragma unroll 1
        for (int s = 0; s < CHUNK; ++s) {
            const u64* hr = hW + cur * (32 * HK_STRIDE);
            u64*       hw = hW + (cur ^ 1) * (32 * HK_STRIDE);

            u64 zif[8], zgo[8];
#pragma unroll
            for (int b = 0; b < 8; ++b) { zif[b] = bif; zgo[b] = bgo; }

            // ---- input projection: broadcast dup-x, per-lane smem weights ----
#pragma unroll
            for (int i = 0; i < I_SZ; ++i) {
                const ulonglong2 wv = wi_sm[i * 32 + lane];
                const u64* xr = xW + s * XT_STRIDE + i * XI_STRIDE;
#pragma unroll
                for (int p = 0; p < 4; ++p) {
                    const ulonglong2 xv = *(const ulonglong2*)(xr + 2 * p);
                    zif[2*p+0] = fma2(xv.x, wv.x, zif[2*p+0]);
                    zgo[2*p+0] = fma2(xv.x, wv.y, zgo[2*p+0]);
                    zif[2*p+1] = fma2(xv.y, wv.x, zif[2*p+1]);
                    zgo[2*p+1] = fma2(xv.y, wv.y, zgo[2*p+1]);
                }
            }

            // ---- recurrent projection: register weights, broadcast dup-h ----
#pragma unroll
            for (int k = 0; k < 32; ++k) {
                const u64 wifk = wif[k], wgok = wgo[k];
                const u64* hk = hr + k * HK_STRIDE;
#pragma unroll
                for (int p = 0; p < 4; ++p) {
                    const ulonglong2 hv = *(const ulonglong2*)(hk + 2 * p);
                    zif[2*p+0] = fma2(hv.x, wifk, zif[2*p+0]);
                    zgo[2*p+0] = fma2(hv.x, wgok, zgo[2*p+0]);
                    zif[2*p+1] = fma2(hv.y, wifk, zif[2*p+1]);
                    zgo[2*p+1] = fma2(hv.y, wgok, zgo[2*p+1]);
                }
            }

            // ---- gates + state update (8 independent chains) ----
#pragma unroll
            for (int b = 0; b < 8; ++b) {
                float zi, zf, zg, zo;
                unpack2(zif[b], zi, zf); unpack2(zgo[b], zg, zo);
                cs[b] = fmaf(sig_h(zf), cs[b], sig_h(zi) * tanhap(zg));
                hs[b] = sig_h(zo) * tanhap(cs[b]);
            }

            // ---- store duplicated h for next step: 4x STS.128, stride-10 ----
            {
                u64* hd = hw + lane * HK_STRIDE;
                *(float4*)(hd + 0) = make_float4(hs[0], hs[0], hs[1], hs[1]);
                *(float4*)(hd + 2) = make_float4(hs[2], hs[2], hs[3], hs[3]);
                *(float4*)(hd + 4) = make_float4(hs[4], hs[4], hs[5], hs[5]);
                *(float4*)(hd + 6) = make_float4(hs[6], hs[6], hs[7], hs[7]);
            }
            cur ^= 1;
            __syncwarp();
        }
    }

    // ---- output head: out[b] = sum_j h[b][j]*W_out[j] + b_out ----
    const float wo = W_out[lane];
    float v[8];
#pragma unroll
    for (int b = 0; b < 8; ++b) v[b] = hs[b] * wo;
#pragma unroll
    for (int off = 16; off; off >>= 1) {
#pragma unroll
        for (int b = 0; b < 8; ++b)
            v[b] += __shfl_xor_sync(0xffffffffu, v[b], off);
    }
    if (lane == 0) {
        const float bout = b_out[0];
        const int bb = blockIdx.x * 32 + warp * 8;
#pragma unroll
        for (int b = 0; b < 8; ++b) out[bb + b] = v[b] + bout;
    }
}

extern "C" void kernel_launch(void* const* d_in, const int* in_sizes, int n_in,
                              void* d_out, int out_size)
{
    const float* x     = (const float*)d_in[0];
    const float* W_ih  = (const float*)d_in[1];
    const float* W_hh  = (const float*)d_in[2];
    const float* b_ih  = (const float*)d_in[3];
    const float* b_hh  = (const float*)d_in[4];
    const float* W_out = (const float*)d_in[5];
    const float* b_out = (const float*)d_in[6];
    float* out = (float*)d_out;

    lstm_kernel<<<B_TOT / 32, 128>>>(x, W_ih, W_hh, b_ih, b_hh, W_out, b_out, out);
}